// round 10
// baseline (speedup 1.0000x reference)
#include <cuda_runtime.h>
#include <cstdint>

#define KDIM     256
#define NCOLS    40          // 10 classes * 4 centroids
#define NCLASSES 10
#define KCENT    4
#define NW       6           // warps per CTA
#define BM       (NW * 16)   // 96 rows per tile (each warp: one m16 tile)
#define NTHREADS (NW * 32)   // 192
#define NBUF     3           // half-K stage buffers per warp
#define HALF_F4  512         // one half-stage: 16 rows * 32 units (float4)
#define BUF_BYTES 8192       // HALF_F4 * 16

// Pre-scattered, normalized, tf32-rounded B fragments.
// float4 index = ((c*5 + nt)*2 + ii)*32 + lane  (lane = g*4 + q), components f,
// holding B_nat[n = nt*8 + g][nat_k = c*32 + 16*ii + 4*q + f]
__device__ float4 g_Bfrag[8 * 5 * 2 * 32];
// Normalized centroids, natural layout [v][k] (tail kernel).
__device__ float g_centsN[NCOLS * KDIM];

// ---------------------------------------------------------------------------
// Prep: normalize the 40 centroids (x / max(||x||,1e-12)); emit tf32-rounded
// MMA fragments + natural fp32 copy.
// ---------------------------------------------------------------------------
__global__ void prep_kernel(const float* __restrict__ cents) {
    const int w    = threadIdx.x >> 5;
    const int lane = threadIdx.x & 31;
    float* Bf = reinterpret_cast<float*>(g_Bfrag);
    for (int v = w; v < NCOLS; v += (int)(blockDim.x >> 5)) {
        const float* src = cents + v * KDIM;
        float vals[8];
        float s = 0.f;
        #pragma unroll
        for (int i = 0; i < 8; i++) {
            vals[i] = src[lane + 32 * i];
            s += vals[i] * vals[i];
        }
        #pragma unroll
        for (int off = 16; off; off >>= 1)
            s += __shfl_xor_sync(0xffffffffu, s, off);
        const float inv = 1.f / fmaxf(sqrtf(s), 1e-12f);
        const int nt = v >> 3;
        const int g  = v & 7;
        #pragma unroll
        for (int i = 0; i < 8; i++) {
            const int k = lane + 32 * i;
            const float x = vals[i] * inv;
            g_centsN[v * KDIM + k] = x;
            uint32_t u;
            asm("cvt.rna.tf32.f32 %0, %1;" : "=r"(u) : "f"(x));
            const int c   = k >> 5;
            const int w32 = k & 31;
            const int ii  = w32 >> 4;
            const int q   = (w32 >> 2) & 3;
            const int f   = w32 & 3;
            Bf[((((c * 5 + nt) * 2 + ii) * 32) + (g * 4 + q)) * 4 + f] =
                __uint_as_float(u);
        }
    }
}

__device__ __forceinline__ void cp16(uint32_t dst, const float* src) {
    asm volatile("cp.async.cg.shared.global [%0], [%1], 16;"
                 :: "r"(dst), "l"(src) : "memory");
}
__device__ __forceinline__ void cp_commit() {
    asm volatile("cp.async.commit_group;" ::: "memory");
}
__device__ __forceinline__ void cp_wait0() {
    asm volatile("cp.async.wait_group 0;" ::: "memory");
}
__device__ __forceinline__ void cp_wait1() {
    asm volatile("cp.async.wait_group 1;" ::: "memory");
}

// ---------------------------------------------------------------------------
// Hot kernel: persistent CTAs (1/SM). Each warp owns one m16 tile (16 rows).
// A is streamed ROW-CONTIGUOUSLY: each cp.async instruction covers one row's
// 512B half-K span (DRAM page-friendly), landing in a bank-swizzled smem
// stage. 3 half-K buffers per warp; 1 commit group per half; wait_group 1.
// B conflict-free LDS.128 fragments; mma m16n8k8 tf32; fused 1 - max_k.
// smem: A 6 warps * 3 * 8KB = 144KB + B 40KB = 184KB.
// ---------------------------------------------------------------------------
extern __shared__ float4 smem4[];

__global__ void __launch_bounds__(NTHREADS, 1)
gemm_kernel(const float* __restrict__ codes, float* __restrict__ out,
            int ntiles) {
    float4* const Asm = smem4;                         // 9216 float4
    float4* const Bsm = smem4 + NW * NBUF * HALF_F4;   // 2560 float4

    const int tid  = threadIdx.x;
    const int lane = tid & 31;
    const int warp = tid >> 5;
    const int g = lane >> 2;     // 0..7
    const int q = lane & 3;      // 0..3
    const int b = blockIdx.x;
    const int G = gridDim.x;

    const int myn = (ntiles > b) ? ((ntiles - b - 1) / G + 1) : 0;
    if (myn == 0) return;
    const int total2 = myn * 2;                        // half-stages

    // ---- issue state ----
    const float* ibase = codes + ((long)b * BM + warp * 16) * KDIM + 4 * lane;
    int icnt = 0;   // halves issued
    int ibuf = 0;   // next buffer
    const uint32_t wbyte = (uint32_t)__cvta_generic_to_shared(Asm)
                         + (uint32_t)warp * (NBUF * BUF_BYTES);
    const uint32_t off_e = (uint32_t)lane * 16u;          // even-row lane slot
    const uint32_t off_o = (uint32_t)(lane ^ 4) * 16u;    // odd-row (swizzled)

    // Issue quarter cl (rows 4cl..4cl+3) of half 'icnt'; each cp16 instruction
    // is one row's contiguous 512B. Commit + advance at cl==3.
    auto issue_quarter = [&](int cl) {
        if (icnt >= total2) return;
        const uint32_t d = wbyte + (uint32_t)ibuf * BUF_BYTES
                         + (uint32_t)cl * 2048u;
        cp16(d +          off_e, ibase + (4 * cl + 0) * KDIM);
        cp16(d + 512u  +  off_o, ibase + (4 * cl + 1) * KDIM);
        cp16(d + 1024u +  off_e, ibase + (4 * cl + 2) * KDIM);
        cp16(d + 1536u +  off_o, ibase + (4 * cl + 3) * KDIM);
        if (cl == 3) {
            cp_commit();
            ibase += (icnt & 1) ? ((long)G * BM * KDIM - 128) : 128;
            icnt++;
            ibuf = (ibuf == NBUF - 1) ? 0 : ibuf + 1;
        }
    };

    // Prologue: two halves in flight.
    #pragma unroll
    for (int h = 0; h < 2; h++)
        #pragma unroll
        for (int cl = 0; cl < 4; cl++)
            issue_quarter(cl);

    // Stage B fragments (once, persistent).
    for (int i = tid; i < 2560; i += NTHREADS)
        Bsm[i] = g_Bfrag[i];
    __syncthreads();

    // per-thread swizzled unit offsets (row parity of g == parity of g+8)
    const int s4 = (g & 1) << 2;
    const int e0 = q ^ s4;          // i=0 unit low bits
    const int e1 = (q + 4) ^ s4;    // i=1 unit low bits
    const float4* const aw = Asm + warp * (NBUF * HALF_F4);

    for (int ti = 0; ti < myn; ti++) {
        float acc[5][4];
        #pragma unroll
        for (int n = 0; n < 5; n++)
            #pragma unroll
            for (int j = 0; j < 4; j++) acc[n][j] = 0.f;

        #pragma unroll
        for (int hf = 0; hf < 2; hf++) {
            const int hs = ti * 2 + hf;
            if (hs == total2 - 1) cp_wait0(); else cp_wait1();
            __syncwarp();
            const float4* const ab = aw + (hs % 3) * HALF_F4;

            #pragma unroll
            for (int cl = 0; cl < 4; cl++) {
                issue_quarter(cl);

                const float4 p00 = ab[g * 32 + 8 * cl + e0];        // row g, i0
                const float4 p01 = ab[g * 32 + 8 * cl + e1];        // row g, i1
                const float4 p10 = ab[(g + 8) * 32 + 8 * cl + e0];  // row g+8
                const float4 p11 = ab[(g + 8) * 32 + 8 * cl + e1];

                const int c = hf * 4 + cl;    // global k-chunk for B
                #pragma unroll
                for (int nt = 0; nt < 5; nt++) {
                    const float4 wb0 = Bsm[((c * 5 + nt) * 2 + 0) * 32 + lane];
                    const float4 wb1 = Bsm[((c * 5 + nt) * 2 + 1) * 32 + lane];
                    #pragma unroll
                    for (int m = 0; m < 4; m++) {
                        const float4 wb  = (m < 2) ? wb0 : wb1;
                        const float4 pr0 = (m < 2) ? p00 : p01;
                        const float4 pr1 = (m < 2) ? p10 : p11;
                        const uint32_t b0 = __float_as_uint((m & 1) ? wb.z : wb.x);
                        const uint32_t b1 = __float_as_uint((m & 1) ? wb.w : wb.y);
                        const uint32_t a0 = __float_as_uint((m & 1) ? pr0.z : pr0.x);
                        const uint32_t a1 = __float_as_uint((m & 1) ? pr1.z : pr1.x);
                        const uint32_t a2 = __float_as_uint((m & 1) ? pr0.w : pr0.y);
                        const uint32_t a3 = __float_as_uint((m & 1) ? pr1.w : pr1.y);
                        asm volatile(
                            "mma.sync.aligned.m16n8k8.row.col.f32.tf32.tf32.f32 "
                            "{%0,%1,%2,%3}, {%4,%5,%6,%7}, {%8,%9}, {%0,%1,%2,%3};"
                            : "+f"(acc[nt][0]), "+f"(acc[nt][1]),
                              "+f"(acc[nt][2]), "+f"(acc[nt][3])
                            : "r"(a0), "r"(a1), "r"(a2), "r"(a3),
                              "r"(b0), "r"(b1));
                    }
                }
            }
        }

        // Epilogue: acc[nt][0,1] -> row row0 ; acc[nt][2,3] -> row0+8.
        const long row0 = (long)(b + ti * G) * BM + warp * 16 + g;
        float* const obase = out + row0 * NCLASSES;
        #pragma unroll
        for (int nt = 0; nt < 5; nt++) {
            float m0 = fmaxf(acc[nt][0], acc[nt][1]);
            float m1 = fmaxf(acc[nt][2], acc[nt][3]);
            m0 = fmaxf(m0, __shfl_xor_sync(0xffffffffu, m0, 1));
            m1 = fmaxf(m1, __shfl_xor_sync(0xffffffffu, m1, 1));
            const int cls = nt * 2 + (q >> 1);
            if ((q & 1) == 0) {
                __stcs(obase + cls, 1.f - m0);
                __stcs(obase + 8 * NCLASSES + cls, 1.f - m1);
            }
        }
    }
}

// ---------------------------------------------------------------------------
// Tail: remaining (< BM) rows, plain fp32.
// ---------------------------------------------------------------------------
__global__ void tail_kernel(const float* __restrict__ codes,
                            float* __restrict__ out,
                            long rbase, int nrows) {
    const long row = rbase + threadIdx.x;
    if (row >= nrows) return;
    const float* a = codes + row * KDIM;
    float best[NCLASSES];
    #pragma unroll
    for (int c = 0; c < NCLASSES; c++) best[c] = -1e30f;
    for (int v = 0; v < NCOLS; v++) {
        const float* bp = g_centsN + v * KDIM;
        float s = 0.f;
        for (int k = 0; k < KDIM; k++) s += a[k] * bp[k];
        const int c = v / KCENT;
        best[c] = fmaxf(best[c], s);
    }
    #pragma unroll
    for (int c = 0; c < NCLASSES; c++)
        out[row * NCLASSES + c] = 1.f - best[c];
}

// ---------------------------------------------------------------------------
extern "C" void kernel_launch(void* const* d_in, const int* in_sizes, int n_in,
                              void* d_out, int out_size) {
    const float* codes = (const float*)d_in[0];   // (B, 256) f32
    const float* cents = (const float*)d_in[1];   // (10, 4, 256) f32
    float* out = (float*)d_out;                   // (B, 10) f32

    const int nrows  = in_sizes[0] / KDIM;
    const int ntiles = nrows / BM;
    const int tail   = nrows - ntiles * BM;

    const int smem_bytes = (NW * NBUF * HALF_F4 + 2560) * (int)sizeof(float4);

    cudaFuncSetAttribute(gemm_kernel,
                         cudaFuncAttributeMaxDynamicSharedMemorySize,
                         smem_bytes);

    int nsm = 0;
    cudaDeviceGetAttribute(&nsm, cudaDevAttrMultiProcessorCount, 0);
    if (nsm <= 0) nsm = 148;

    prep_kernel<<<1, 256>>>(cents);

    if (ntiles > 0) {
        const int grid = ntiles < nsm ? ntiles : nsm;
        gemm_kernel<<<grid, NTHREADS, smem_bytes>>>(codes, out, ntiles);
    }
    if (tail > 0)
        tail_kernel<<<1, 128>>>(codes, out, (long)ntiles * BM, nrows);
}